// round 6
// baseline (speedup 1.0000x reference)
#include <cuda_runtime.h>
#include <cuda_bf16.h>
#include <cstdint>

// out[s,a] = values[index[s,a]]
// index: int32 [33,554,432], values: float [100], out: float [33,554,432]
//
// HBM-bound gather at the roofline. This round: persistent grid-stride CTAs.
//  - grid = 2 CTAs/SM * 148 SMs = 296 -> single wave, no wave transitions,
//    table filled 296x instead of 4096x
//  - tiny single-copy 512B smem table (zero occupancy cost)
//  - MLP = 4 front-batched int4 loads per tile-iteration (32 regs target)
//  - streaming cache hints on both touch-once global streams

static constexpr int VOCAB_MAX       = 128;
static constexpr int THREADS         = 512;
static constexpr int VEC_PER_THREAD  = 4;                        // 4 x int4 = 16 elems/thread
static constexpr int VEC_PER_BLOCK   = THREADS * VEC_PER_THREAD; // 2048 vec4/tile
static constexpr int GRID            = 296;                      // 148 SMs * 2 CTAs

__global__ void __launch_bounds__(THREADS) gather_persist_kernel(
    const int4* __restrict__ idx4,
    const float* __restrict__ values,
    float4* __restrict__ out4,
    int n_vec4,
    int n_values)
{
    __shared__ float s_vals[VOCAB_MAX];
    for (int i = threadIdx.x; i < n_values; i += THREADS) {
        s_vals[i] = values[i];
    }
    __syncthreads();

    const int n_tiles = (n_vec4 + VEC_PER_BLOCK - 1) / VEC_PER_BLOCK;

    for (int tile = blockIdx.x; tile < n_tiles; tile += gridDim.x) {
        int base = tile * VEC_PER_BLOCK + threadIdx.x;

        if (base + (VEC_PER_THREAD - 1) * THREADS < n_vec4) {
            // Fast path: every tile for this shape (8,388,608 = 4096 * 2048).
            int4 v[VEC_PER_THREAD];
            #pragma unroll
            for (int k = 0; k < VEC_PER_THREAD; k++) {
                v[k] = __ldcs(&idx4[base + k * THREADS]);
            }
            #pragma unroll
            for (int k = 0; k < VEC_PER_THREAD; k++) {
                float4 r;
                r.x = s_vals[v[k].x];
                r.y = s_vals[v[k].y];
                r.z = s_vals[v[k].z];
                r.w = s_vals[v[k].w];
                __stcs(&out4[base + k * THREADS], r);
            }
        } else {
            // Tail tile (unused for this shape, kept for safety)
            #pragma unroll
            for (int k = 0; k < VEC_PER_THREAD; k++) {
                int i = base + k * THREADS;
                if (i < n_vec4) {
                    int4 v = __ldcs(&idx4[i]);
                    float4 r;
                    r.x = s_vals[v.x];
                    r.y = s_vals[v.y];
                    r.z = s_vals[v.z];
                    r.w = s_vals[v.w];
                    __stcs(&out4[i], r);
                }
            }
        }
    }
}

__global__ void gather_tail_kernel(
    const int* __restrict__ idx,
    const float* __restrict__ values,
    float* __restrict__ out,
    int start,
    int n_total)
{
    int i = start + blockIdx.x * blockDim.x + threadIdx.x;
    if (i < n_total) {
        out[i] = values[idx[i]];
    }
}

extern "C" void kernel_launch(void* const* d_in, const int* in_sizes, int n_in,
                              void* d_out, int out_size)
{
    const int* index = (const int*)d_in[0];
    const float* values = (const float*)d_in[1];
    float* out = (float*)d_out;

    int n_total = in_sizes[0];          // 33,554,432
    int n_values = in_sizes[1];         // 100
    int n_vec4 = n_total / 4;           // 8,388,608

    gather_persist_kernel<<<GRID, THREADS>>>(
        (const int4*)index, values, (float4*)out, n_vec4, n_values);

    int tail_start = n_vec4 * 4;
    int tail = n_total - tail_start;
    if (tail > 0) {
        int tb = (tail + 255) / 256;
        gather_tail_kernel<<<tb, 256>>>(index, values, out, tail_start, n_total);
    }
}

// round 7
// speedup vs baseline: 1.1088x; 1.1088x over previous
#include <cuda_runtime.h>
#include <cuda_bf16.h>
#include <cstdint>

// out[s,a] = values[index[s,a]]
// index: int32 [33,554,432], values: float [100], out: float [33,554,432]
//
// Converged HBM-bound gather (best measured config = R2):
//  - 256 threads/block, flat grid of 8192 CTAs -> occ 84%, best occ x MLP point
//  - tiny single-copy 512B smem table, one predicated load to fill
//  - MLP = 4 front-batched int4 loads / float4 stores (32 regs)
//  - streaming cache hints on both touch-once global streams
// Measured sweep: MLP=1 41.4us, MLP=8 37.5us (occ loss), 512thr 38.0us,
// persistent 38.2us, replicated table 39.1us -> this config: 37.1us.

static constexpr int VOCAB_MAX       = 128;
static constexpr int THREADS         = 256;
static constexpr int VEC_PER_THREAD  = 4;                        // 4 x int4 = 16 elems/thread
static constexpr int VEC_PER_BLOCK   = THREADS * VEC_PER_THREAD; // 1024 vec4/block

__global__ void __launch_bounds__(THREADS) gather_final_kernel(
    const int4* __restrict__ idx4,
    const float* __restrict__ values,
    float4* __restrict__ out4,
    int n_vec4,
    int n_values)
{
    __shared__ float s_vals[VOCAB_MAX];
    if (threadIdx.x < n_values) {
        s_vals[threadIdx.x] = values[threadIdx.x];
    }
    __syncthreads();

    int base = blockIdx.x * VEC_PER_BLOCK + threadIdx.x;

    if (base + (VEC_PER_THREAD - 1) * THREADS < n_vec4) {
        // Fast path: every block for this shape (8,388,608 / 1024 = 8192).
        int4 v[VEC_PER_THREAD];
        #pragma unroll
        for (int k = 0; k < VEC_PER_THREAD; k++) {
            v[k] = __ldcs(&idx4[base + k * THREADS]);
        }
        #pragma unroll
        for (int k = 0; k < VEC_PER_THREAD; k++) {
            float4 r;
            r.x = s_vals[v[k].x];
            r.y = s_vals[v[k].y];
            r.z = s_vals[v[k].z];
            r.w = s_vals[v[k].w];
            __stcs(&out4[base + k * THREADS], r);
        }
    } else {
        // Guard path (unused for this shape)
        #pragma unroll
        for (int k = 0; k < VEC_PER_THREAD; k++) {
            int i = base + k * THREADS;
            if (i < n_vec4) {
                int4 v = __ldcs(&idx4[i]);
                float4 r;
                r.x = s_vals[v.x];
                r.y = s_vals[v.y];
                r.z = s_vals[v.z];
                r.w = s_vals[v.w];
                __stcs(&out4[i], r);
            }
        }
    }
}

__global__ void gather_tail_kernel(
    const int* __restrict__ idx,
    const float* __restrict__ values,
    float* __restrict__ out,
    int start,
    int n_total)
{
    int i = start + blockIdx.x * blockDim.x + threadIdx.x;
    if (i < n_total) {
        out[i] = values[idx[i]];
    }
}

extern "C" void kernel_launch(void* const* d_in, const int* in_sizes, int n_in,
                              void* d_out, int out_size)
{
    const int* index = (const int*)d_in[0];
    const float* values = (const float*)d_in[1];
    float* out = (float*)d_out;

    int n_total = in_sizes[0];          // 33,554,432
    int n_values = in_sizes[1];         // 100
    int n_vec4 = n_total / 4;           // 8,388,608

    int blocks = (n_vec4 + VEC_PER_BLOCK - 1) / VEC_PER_BLOCK;   // 8192
    gather_final_kernel<<<blocks, THREADS>>>(
        (const int4*)index, values, (float4*)out, n_vec4, n_values);

    // Tail is 0 for this shape (33,554,432 % 4 == 0); launch only if needed.
    int tail_start = n_vec4 * 4;
    int tail = n_total - tail_start;
    if (tail > 0) {
        int tb = (tail + 255) / 256;
        gather_tail_kernel<<<tb, 256>>>(index, values, out, tail_start, n_total);
    }
}

// round 8
// speedup vs baseline: 1.1096x; 1.0007x over previous
#include <cuda_runtime.h>
#include <cuda_bf16.h>
#include <cstdint>

// out[s,a] = values[index[s,a]]
// index: int32 [33,554,432], values: float [100], out: float [33,554,432]
//
// Converged HBM-bound gather (~7.2 TB/s goodput, ~90% of spec).
// This round: 128-thread CTAs (16/SM) — finer CTA granularity against the
// L1tex queue, cheaper barriers; memory pattern identical to the best config.
//  - tiny single-copy 512B smem table
//  - MLP = 4 front-batched int4 loads / float4 stores
//  - streaming cache hints on both touch-once global streams
// Sweep so far (kernel us): MLP1 41.4 | MLP4/256t 37.1-37.4 | MLP8 37.5 |
// 512t 38.0 | persistent 38.2 | replicated-table 39.1.

static constexpr int VOCAB_MAX       = 128;
static constexpr int THREADS         = 128;
static constexpr int VEC_PER_THREAD  = 4;                        // 4 x int4 = 16 elems/thread
static constexpr int VEC_PER_BLOCK   = THREADS * VEC_PER_THREAD; // 512 vec4/block

__global__ void __launch_bounds__(THREADS) gather_128t_kernel(
    const int4* __restrict__ idx4,
    const float* __restrict__ values,
    float4* __restrict__ out4,
    int n_vec4,
    int n_values)
{
    __shared__ float s_vals[VOCAB_MAX];
    if (threadIdx.x < n_values) {
        s_vals[threadIdx.x] = values[threadIdx.x];
    }
    __syncthreads();

    int base = blockIdx.x * VEC_PER_BLOCK + threadIdx.x;

    if (base + (VEC_PER_THREAD - 1) * THREADS < n_vec4) {
        // Fast path: every block for this shape (8,388,608 / 512 = 16384).
        int4 v[VEC_PER_THREAD];
        #pragma unroll
        for (int k = 0; k < VEC_PER_THREAD; k++) {
            v[k] = __ldcs(&idx4[base + k * THREADS]);
        }
        #pragma unroll
        for (int k = 0; k < VEC_PER_THREAD; k++) {
            float4 r;
            r.x = s_vals[v[k].x];
            r.y = s_vals[v[k].y];
            r.z = s_vals[v[k].z];
            r.w = s_vals[v[k].w];
            __stcs(&out4[base + k * THREADS], r);
        }
    } else {
        // Guard path (unused for this shape)
        #pragma unroll
        for (int k = 0; k < VEC_PER_THREAD; k++) {
            int i = base + k * THREADS;
            if (i < n_vec4) {
                int4 v = __ldcs(&idx4[i]);
                float4 r;
                r.x = s_vals[v.x];
                r.y = s_vals[v.y];
                r.z = s_vals[v.z];
                r.w = s_vals[v.w];
                __stcs(&out4[i], r);
            }
        }
    }
}

__global__ void gather_tail_kernel(
    const int* __restrict__ idx,
    const float* __restrict__ values,
    float* __restrict__ out,
    int start,
    int n_total)
{
    int i = start + blockIdx.x * blockDim.x + threadIdx.x;
    if (i < n_total) {
        out[i] = values[idx[i]];
    }
}

extern "C" void kernel_launch(void* const* d_in, const int* in_sizes, int n_in,
                              void* d_out, int out_size)
{
    const int* index = (const int*)d_in[0];
    const float* values = (const float*)d_in[1];
    float* out = (float*)d_out;

    int n_total = in_sizes[0];          // 33,554,432
    int n_values = in_sizes[1];         // 100
    int n_vec4 = n_total / 4;           // 8,388,608

    int blocks = (n_vec4 + VEC_PER_BLOCK - 1) / VEC_PER_BLOCK;   // 16384
    gather_128t_kernel<<<blocks, THREADS>>>(
        (const int4*)index, values, (float4*)out, n_vec4, n_values);

    int tail_start = n_vec4 * 4;
    int tail = n_total - tail_start;
    if (tail > 0) {
        int tb = (tail + 255) / 256;
        gather_tail_kernel<<<tb, 256>>>(index, values, out, tail_start, n_total);
    }
}